// round 5
// baseline (speedup 1.0000x reference)
#include <cuda_runtime.h>
#include <cuda_bf16.h>
#include <cstdint>

#define N_FEAT 256          // IN_F == OUT_F == 256
#define OUT_STRIDE 512      // concat([ft_input, ft_neighbor], axis=1)

#define MAX_NODES 100000
#define MAX_EDGES 3200000
#define SCAN_BLK 1024
#define MAX_SCAN_BLOCKS ((MAX_NODES + SCAN_BLK - 1) / SCAN_BLK)   // 98

// ---------------------------------------------------------------------------
// Scratch (device globals)
// ---------------------------------------------------------------------------
__device__ int   d_cursor[MAX_NODES];
__device__ int   d_rowstart[MAX_NODES + 1];
__device__ int   d_blocksum[MAX_SCAN_BLOCKS];
__device__ int   d_srcsorted[MAX_EDGES];
__device__ float d_valsorted[MAX_EDGES];
// split-bf16 operands
__device__ __nv_bfloat16 d_xhi[(size_t)MAX_NODES * N_FEAT];
__device__ __nv_bfloat16 d_xlo[(size_t)MAX_NODES * N_FEAT];
__device__ __nv_bfloat16 d_wthi[N_FEAT * N_FEAT];   // W^T : [n][k]
__device__ __nv_bfloat16 d_wtlo[N_FEAT * N_FEAT];

// ---------------------------------------------------------------------------
// mma.sync helpers (classic HMMA path — valid on compute_103 baseline)
// ---------------------------------------------------------------------------
__device__ __forceinline__ uint32_t smem_u32(const void* p) {
    uint32_t a;
    asm("{ .reg .u64 t; cvta.to.shared.u64 t, %1; cvt.u32.u64 %0, t; }"
        : "=r"(a) : "l"(p));
    return a;
}
__device__ __forceinline__ void ldsm_x4(uint32_t* r, uint32_t addr) {
    asm volatile("ldmatrix.sync.aligned.m8n8.x4.shared.b16 {%0,%1,%2,%3}, [%4];"
                 : "=r"(r[0]), "=r"(r[1]), "=r"(r[2]), "=r"(r[3]) : "r"(addr));
}
__device__ __forceinline__ void mma_bf16(float* c, const uint32_t* a, const uint32_t* b) {
    asm volatile(
        "mma.sync.aligned.m16n8k16.row.col.f32.bf16.bf16.f32 "
        "{%0,%1,%2,%3}, {%4,%5,%6,%7}, {%8,%9}, {%0,%1,%2,%3};"
        : "+f"(c[0]), "+f"(c[1]), "+f"(c[2]), "+f"(c[3])
        : "r"(a[0]), "r"(a[1]), "r"(a[2]), "r"(a[3]), "r"(b[0]), "r"(b[1]));
}

// ---------------------------------------------------------------------------
// Conversion kernels: f32 -> (hi, lo) bf16 split
// ---------------------------------------------------------------------------
__global__ void convert_x_kernel(const float* __restrict__ x, int total4) {
    int i = blockIdx.x * blockDim.x + threadIdx.x;
    if (i >= total4) return;
    float4 v = reinterpret_cast<const float4*>(x)[i];
    __nv_bfloat16 h0 = __float2bfloat16(v.x), h1 = __float2bfloat16(v.y);
    __nv_bfloat16 h2 = __float2bfloat16(v.z), h3 = __float2bfloat16(v.w);
    __nv_bfloat16 l0 = __float2bfloat16(v.x - __bfloat162float(h0));
    __nv_bfloat16 l1 = __float2bfloat16(v.y - __bfloat162float(h1));
    __nv_bfloat16 l2 = __float2bfloat16(v.z - __bfloat162float(h2));
    __nv_bfloat16 l3 = __float2bfloat16(v.w - __bfloat162float(h3));
    reinterpret_cast<__nv_bfloat162*>(d_xhi)[i * 2]     = __nv_bfloat162(h0, h1);
    reinterpret_cast<__nv_bfloat162*>(d_xhi)[i * 2 + 1] = __nv_bfloat162(h2, h3);
    reinterpret_cast<__nv_bfloat162*>(d_xlo)[i * 2]     = __nv_bfloat162(l0, l1);
    reinterpret_cast<__nv_bfloat162*>(d_xlo)[i * 2 + 1] = __nv_bfloat162(l2, l3);
}

__global__ void convert_w_kernel(const float* __restrict__ w) {
    int idx = blockIdx.x * blockDim.x + threadIdx.x;   // over 256*256
    if (idx >= N_FEAT * N_FEAT) return;
    int n = idx >> 8, k = idx & 255;
    float v = w[k * N_FEAT + n];                        // transpose -> [n][k]
    __nv_bfloat16 h = __float2bfloat16(v);
    __nv_bfloat16 l = __float2bfloat16(v - __bfloat162float(h));
    d_wthi[n * N_FEAT + k] = h;
    d_wtlo[n * N_FEAT + k] = l;
}

// ---------------------------------------------------------------------------
// CSR build (unchanged)
// ---------------------------------------------------------------------------
__global__ void zero_count_kernel(int n_nodes) {
    int i = blockIdx.x * blockDim.x + threadIdx.x;
    if (i < n_nodes) d_cursor[i] = 0;
}
__global__ void hist_kernel(const int* __restrict__ edst, int n_edges) {
    int e = blockIdx.x * blockDim.x + threadIdx.x;
    if (e < n_edges) atomicAdd(&d_cursor[edst[e]], 1);
}
__global__ __launch_bounds__(SCAN_BLK)
void scan1_kernel(int n_nodes) {
    __shared__ int tmp[SCAN_BLK];
    int tid = threadIdx.x;
    int i   = blockIdx.x * SCAN_BLK + tid;
    int v   = (i < n_nodes) ? d_cursor[i] : 0;
    tmp[tid] = v;
    __syncthreads();
#pragma unroll
    for (int off = 1; off < SCAN_BLK; off <<= 1) {
        int t = (tid >= off) ? tmp[tid - off] : 0;
        __syncthreads();
        tmp[tid] += t;
        __syncthreads();
    }
    if (i < n_nodes) d_rowstart[i] = tmp[tid] - v;
    if (tid == SCAN_BLK - 1) d_blocksum[blockIdx.x] = tmp[tid];
}
__global__ void scan2_kernel(int n_blocks) {
    __shared__ int tmp[128];
    int tid = threadIdx.x;
    int v   = (tid < n_blocks) ? d_blocksum[tid] : 0;
    tmp[tid] = v;
    __syncthreads();
#pragma unroll
    for (int off = 1; off < 128; off <<= 1) {
        int t = (tid >= off) ? tmp[tid - off] : 0;
        __syncthreads();
        tmp[tid] += t;
        __syncthreads();
    }
    if (tid < n_blocks) d_blocksum[tid] = tmp[tid] - v;
}
__global__ void scan3_kernel(int n_nodes, int n_edges) {
    int i = blockIdx.x * blockDim.x + threadIdx.x;
    if (i < n_nodes) {
        int g = d_rowstart[i] + d_blocksum[i / SCAN_BLK];
        d_rowstart[i] = g;
        d_cursor[i]   = g;
    }
    if (i == 0) d_rowstart[n_nodes] = n_edges;
}
__global__ void reorder_kernel(const int* __restrict__ esrc,
                               const int* __restrict__ edst,
                               const float* __restrict__ eval_, int n_edges) {
    int e = blockIdx.x * blockDim.x + threadIdx.x;
    if (e >= n_edges) return;
    int pos = atomicAdd(&d_cursor[edst[e]], 1);
    d_srcsorted[pos] = esrc[e];
    d_valsorted[pos] = eval_[e];
}

// ---------------------------------------------------------------------------
// HMMA GEMM: out[:, 0:256] = X @ W via split-bf16 (3 terms).
// Block: 64 rows x 256 cols, 8 warps (2 m x 4 n), warp tile 32x64.
// K loop: 8 chunks of 32. A tile [64][32], B tile [256][32] ([n][k]).
// XOR swizzle on 16B units: c' = c ^ ((row>>1)&3)  (4 units/row).
// ---------------------------------------------------------------------------
#define SWU(r, c) ((c) ^ (((r) >> 1) & 3))

__global__ __launch_bounds__(256, 2)
void gemm_mma_kernel(float* __restrict__ out, int n_rows) {
    __shared__ __nv_bfloat16 sAhi[64][32], sAlo[64][32];
    __shared__ __nv_bfloat16 sBhi[256][32], sBlo[256][32];

    const int tid  = threadIdx.x;
    const int wid  = tid >> 5;
    const int lane = tid & 31;
    const int wm   = wid >> 2;          // 0..1
    const int wn   = wid & 3;           // 0..3
    const int rowBase = blockIdx.x * 64;

    float acc[2][8][4];
#pragma unroll
    for (int mi = 0; mi < 2; mi++)
#pragma unroll
        for (int j = 0; j < 8; j++)
#pragma unroll
            for (int q = 0; q < 4; q++) acc[mi][j][q] = 0.f;

    for (int kc0 = 0; kc0 < N_FEAT; kc0 += 32) {
        __syncthreads();
        // A tile: 64 rows x 4 units, 256 threads -> 1 pass
        {
            int r = tid >> 2, c = tid & 3;
            int cs = SWU(r, c);
            int gr = rowBase + r;
            uint4 vh = make_uint4(0, 0, 0, 0), vl = make_uint4(0, 0, 0, 0);
            if (gr < n_rows) {
                size_t gp = (size_t)gr * N_FEAT + kc0 + c * 8;
                vh = *reinterpret_cast<const uint4*>(&d_xhi[gp]);
                vl = *reinterpret_cast<const uint4*>(&d_xlo[gp]);
            }
            *reinterpret_cast<uint4*>(&sAhi[r][cs * 8]) = vh;
            *reinterpret_cast<uint4*>(&sAlo[r][cs * 8]) = vl;
        }
        // B tile: 256 rows x 4 units, 4 passes
#pragma unroll
        for (int p = 0; p < 4; p++) {
            int r = (tid >> 2) + p * 64, c = tid & 3;
            int cs = SWU(r, c);
            size_t gp = (size_t)r * N_FEAT + kc0 + c * 8;
            *reinterpret_cast<uint4*>(&sBhi[r][cs * 8]) =
                *reinterpret_cast<const uint4*>(&d_wthi[gp]);
            *reinterpret_cast<uint4*>(&sBlo[r][cs * 8]) =
                *reinterpret_cast<const uint4*>(&d_wtlo[gp]);
        }
        __syncthreads();

#pragma unroll
        for (int ks = 0; ks < 2; ks++) {
            // A fragments: 2 m16 tiles, hi+lo
            uint32_t ahi[2][4], alo[2][4];
#pragma unroll
            for (int mi = 0; mi < 2; mi++) {
                int r = wm * 32 + mi * 16 + (lane & 15);
                int c = ks * 2 + (lane >> 4);
                int cs = SWU(r, c);
                ldsm_x4(ahi[mi], smem_u32(&sAhi[r][cs * 8]));
                ldsm_x4(alo[mi], smem_u32(&sAlo[r][cs * 8]));
            }
#pragma unroll
            for (int nj = 0; nj < 4; nj++) {
                // B fragments: n16 region (two n8 tiles), hi+lo
                int r = wn * 64 + nj * 16 + (lane & 7) + (lane >> 4) * 8;
                int c = ks * 2 + ((lane >> 3) & 1);
                int cs = SWU(r, c);
                uint32_t bhi[4], blo[4];
                ldsm_x4(bhi, smem_u32(&sBhi[r][cs * 8]));
                ldsm_x4(blo, smem_u32(&sBlo[r][cs * 8]));
#pragma unroll
                for (int mi = 0; mi < 2; mi++) {
#pragma unroll
                    for (int sub = 0; sub < 2; sub++) {
                        float* c4 = acc[mi][nj * 2 + sub];
                        mma_bf16(c4, ahi[mi], bhi + sub * 2);
                        mma_bf16(c4, ahi[mi], blo + sub * 2);
                        mma_bf16(c4, alo[mi], bhi + sub * 2);
                    }
                }
            }
        }
    }

    // Epilogue: c-frag: {c0,c1} row = l/4, col = 2*(l%4); {c2,c3} row + 8.
#pragma unroll
    for (int mi = 0; mi < 2; mi++) {
        int r0 = rowBase + wm * 32 + mi * 16 + (lane >> 2);
        int r1 = r0 + 8;
#pragma unroll
        for (int j = 0; j < 8; j++) {
            int col = wn * 64 + j * 8 + (lane & 3) * 2;
            if (r0 < n_rows)
                *reinterpret_cast<float2*>(out + (size_t)r0 * OUT_STRIDE + col) =
                    make_float2(acc[mi][j][0], acc[mi][j][1]);
            if (r1 < n_rows)
                *reinterpret_cast<float2*>(out + (size_t)r1 * OUT_STRIDE + col) =
                    make_float2(acc[mi][j][2], acc[mi][j][3]);
        }
    }
}

// ---------------------------------------------------------------------------
// Per-dst accumulate (unchanged): one warp per node, no atomics.
// ---------------------------------------------------------------------------
__global__ __launch_bounds__(256)
void accumulate_kernel(float* __restrict__ out, int n_nodes) {
    int w    = (blockIdx.x * blockDim.x + threadIdx.x) >> 5;
    int lane = threadIdx.x & 31;
    if (w >= n_nodes) return;

    int beg = d_rowstart[w];
    int end = d_rowstart[w + 1];

    float acc[8];
#pragma unroll
    for (int i = 0; i < 8; i++) acc[i] = 0.f;

    int i = beg;
    for (; i + 1 < end; i += 2) {
        int   s0 = __ldg(&d_srcsorted[i]);
        float v0 = __ldg(&d_valsorted[i]);
        int   s1 = __ldg(&d_srcsorted[i + 1]);
        float v1 = __ldg(&d_valsorted[i + 1]);
        const float4* p0 = reinterpret_cast<const float4*>(out + (size_t)s0 * OUT_STRIDE + lane * 8);
        const float4* p1 = reinterpret_cast<const float4*>(out + (size_t)s1 * OUT_STRIDE + lane * 8);
        float4 a0 = __ldg(p0), b0 = __ldg(p0 + 1);
        float4 a1 = __ldg(p1), b1 = __ldg(p1 + 1);
        acc[0] += v0 * a0.x; acc[1] += v0 * a0.y; acc[2] += v0 * a0.z; acc[3] += v0 * a0.w;
        acc[4] += v0 * b0.x; acc[5] += v0 * b0.y; acc[6] += v0 * b0.z; acc[7] += v0 * b0.w;
        acc[0] += v1 * a1.x; acc[1] += v1 * a1.y; acc[2] += v1 * a1.z; acc[3] += v1 * a1.w;
        acc[4] += v1 * b1.x; acc[5] += v1 * b1.y; acc[6] += v1 * b1.z; acc[7] += v1 * b1.w;
    }
    if (i < end) {
        int   s0 = __ldg(&d_srcsorted[i]);
        float v0 = __ldg(&d_valsorted[i]);
        const float4* p0 = reinterpret_cast<const float4*>(out + (size_t)s0 * OUT_STRIDE + lane * 8);
        float4 a0 = __ldg(p0), b0 = __ldg(p0 + 1);
        acc[0] += v0 * a0.x; acc[1] += v0 * a0.y; acc[2] += v0 * a0.z; acc[3] += v0 * a0.w;
        acc[4] += v0 * b0.x; acc[5] += v0 * b0.y; acc[6] += v0 * b0.z; acc[7] += v0 * b0.w;
    }

    float* o = out + (size_t)w * OUT_STRIDE + N_FEAT + lane * 8;
    *reinterpret_cast<float4*>(o)     = make_float4(acc[0], acc[1], acc[2], acc[3]);
    *reinterpret_cast<float4*>(o + 4) = make_float4(acc[4], acc[5], acc[6], acc[7]);
}

// ---------------------------------------------------------------------------
// Launch
// ---------------------------------------------------------------------------
extern "C" void kernel_launch(void* const* d_in, const int* in_sizes, int n_in,
                              void* d_out, int out_size) {
    const float* input_   = (const float*)d_in[0];
    const int*   edge_src = (const int*)d_in[1];
    const int*   edge_dst = (const int*)d_in[2];
    const float* edge_val = (const float*)d_in[3];
    const float* weight   = (const float*)d_in[4];
    float*       out      = (float*)d_out;

    const int n_nodes = in_sizes[0] / N_FEAT;
    const int n_edges = in_sizes[1];

    const int eb = (n_edges + 255) / 256;
    const int nb = (n_nodes + 255) / 256;
    const int scan_blocks = (n_nodes + SCAN_BLK - 1) / SCAN_BLK;

    // split-bf16 operand prep
    int total4 = n_nodes * (N_FEAT / 4);
    convert_x_kernel<<<(total4 + 255) / 256, 256>>>(input_, total4);
    convert_w_kernel<<<(N_FEAT * N_FEAT + 255) / 256, 256>>>(weight);

    // CSR build
    zero_count_kernel<<<nb, 256>>>(n_nodes);
    hist_kernel<<<eb, 256>>>(edge_dst, n_edges);
    scan1_kernel<<<scan_blocks, SCAN_BLK>>>(n_nodes);
    scan2_kernel<<<1, 128>>>(scan_blocks);
    scan3_kernel<<<nb, 256>>>(n_nodes, n_edges);
    reorder_kernel<<<eb, 256>>>(edge_src, edge_dst, edge_val, n_edges);

    // ft_input = X @ W  (HMMA split-bf16)  -> out[:, 0:256]
    int gemm_blocks = (n_nodes + 63) / 64;
    gemm_mma_kernel<<<gemm_blocks, 256>>>(out, n_nodes);

    // ft_neighbor = A @ ft_input -> out[:, 256:512]
    int acc_blocks = (n_nodes * 32 + 255) / 256;
    accumulate_kernel<<<acc_blocks, 256>>>(out, n_nodes);
}

// round 6
// speedup vs baseline: 1.4956x; 1.4956x over previous
#include <cuda_runtime.h>
#include <cuda_bf16.h>
#include <cstdint>

#define N_FEAT 256          // IN_F == OUT_F == 256
#define OUT_STRIDE 512      // concat([ft_input, ft_neighbor], axis=1)

#define MAX_NODES 100000
#define MAX_EDGES 3200000
#define SCAN_BLK 1024
#define MAX_SCAN_BLOCKS ((MAX_NODES + SCAN_BLK - 1) / SCAN_BLK)   // 98

// ---------------------------------------------------------------------------
// Scratch (device globals)
// ---------------------------------------------------------------------------
__device__ int                d_cursor[MAX_NODES];
__device__ int                d_rowstart[MAX_NODES + 1];
__device__ int                d_blocksum[MAX_SCAN_BLOCKS];
__device__ unsigned long long d_edgepack[MAX_EDGES];   // src | (valbits << 32)
// split-bf16 operands
__device__ __nv_bfloat16 d_xhi[(size_t)MAX_NODES * N_FEAT];
__device__ __nv_bfloat16 d_xlo[(size_t)MAX_NODES * N_FEAT];
__device__ __nv_bfloat16 d_wthi[N_FEAT * N_FEAT];   // W^T : [n][k]
__device__ __nv_bfloat16 d_wtlo[N_FEAT * N_FEAT];

// ---------------------------------------------------------------------------
// PTX helpers (baseline PTX only — valid on compute_103)
// ---------------------------------------------------------------------------
__device__ __forceinline__ uint32_t smem_u32(const void* p) {
    uint32_t a;
    asm("{ .reg .u64 t; cvta.to.shared.u64 t, %1; cvt.u32.u64 %0, t; }"
        : "=r"(a) : "l"(p));
    return a;
}
__device__ __forceinline__ void ldsm_x4(uint32_t* r, uint32_t addr) {
    asm volatile("ldmatrix.sync.aligned.m8n8.x4.shared.b16 {%0,%1,%2,%3}, [%4];"
                 : "=r"(r[0]), "=r"(r[1]), "=r"(r[2]), "=r"(r[3]) : "r"(addr));
}
__device__ __forceinline__ void mma_bf16(float* c, const uint32_t* a, const uint32_t* b) {
    asm volatile(
        "mma.sync.aligned.m16n8k16.row.col.f32.bf16.bf16.f32 "
        "{%0,%1,%2,%3}, {%4,%5,%6,%7}, {%8,%9}, {%0,%1,%2,%3};"
        : "+f"(c[0]), "+f"(c[1]), "+f"(c[2]), "+f"(c[3])
        : "r"(a[0]), "r"(a[1]), "r"(a[2]), "r"(a[3]), "r"(b[0]), "r"(b[1]));
}
#define CP_ASYNC16(dst, src) \
    asm volatile("cp.async.cg.shared.global [%0], [%1], 16;" :: "r"(dst), "l"(src))
#define CP_COMMIT() asm volatile("cp.async.commit_group;" ::: "memory")
#define CP_WAIT(n)  asm volatile("cp.async.wait_group %0;" :: "n"(n) : "memory")

// XOR swizzle on 16B units (4 units per 64B row): conflict-free STS + LDSM.
#define SWU(r, c) ((c) ^ (((r) >> 1) & 3))
#define TOFF(r, c) ((uint32_t)(((r) * 4 + SWU(r, c)) * 16))

// ---------------------------------------------------------------------------
// Conversion kernels: f32 -> (hi, lo) bf16 split
// ---------------------------------------------------------------------------
__global__ void convert_x_kernel(const float* __restrict__ x, int total4) {
    int i = blockIdx.x * blockDim.x + threadIdx.x;
    if (i >= total4) return;
    float4 v = reinterpret_cast<const float4*>(x)[i];
    __nv_bfloat16 h0 = __float2bfloat16(v.x), h1 = __float2bfloat16(v.y);
    __nv_bfloat16 h2 = __float2bfloat16(v.z), h3 = __float2bfloat16(v.w);
    __nv_bfloat16 l0 = __float2bfloat16(v.x - __bfloat162float(h0));
    __nv_bfloat16 l1 = __float2bfloat16(v.y - __bfloat162float(h1));
    __nv_bfloat16 l2 = __float2bfloat16(v.z - __bfloat162float(h2));
    __nv_bfloat16 l3 = __float2bfloat16(v.w - __bfloat162float(h3));
    reinterpret_cast<__nv_bfloat162*>(d_xhi)[i * 2]     = __nv_bfloat162(h0, h1);
    reinterpret_cast<__nv_bfloat162*>(d_xhi)[i * 2 + 1] = __nv_bfloat162(h2, h3);
    reinterpret_cast<__nv_bfloat162*>(d_xlo)[i * 2]     = __nv_bfloat162(l0, l1);
    reinterpret_cast<__nv_bfloat162*>(d_xlo)[i * 2 + 1] = __nv_bfloat162(l2, l3);
}

__global__ void convert_w_kernel(const float* __restrict__ w) {
    int idx = blockIdx.x * blockDim.x + threadIdx.x;   // over 256*256
    if (idx >= N_FEAT * N_FEAT) return;
    int n = idx >> 8, k = idx & 255;
    float v = w[k * N_FEAT + n];                        // transpose -> [n][k]
    __nv_bfloat16 h = __float2bfloat16(v);
    __nv_bfloat16 l = __float2bfloat16(v - __bfloat162float(h));
    d_wthi[n * N_FEAT + k] = h;
    d_wtlo[n * N_FEAT + k] = l;
}

// ---------------------------------------------------------------------------
// CSR build
// ---------------------------------------------------------------------------
__global__ void zero_count_kernel(int n_nodes) {
    int i = blockIdx.x * blockDim.x + threadIdx.x;
    if (i < n_nodes) d_cursor[i] = 0;
}
__global__ void hist_kernel(const int* __restrict__ edst, int n_edges) {
    int e = blockIdx.x * blockDim.x + threadIdx.x;
    if (e < n_edges) atomicAdd(&d_cursor[edst[e]], 1);
}
__global__ __launch_bounds__(SCAN_BLK)
void scan1_kernel(int n_nodes) {
    __shared__ int tmp[SCAN_BLK];
    int tid = threadIdx.x;
    int i   = blockIdx.x * SCAN_BLK + tid;
    int v   = (i < n_nodes) ? d_cursor[i] : 0;
    tmp[tid] = v;
    __syncthreads();
#pragma unroll
    for (int off = 1; off < SCAN_BLK; off <<= 1) {
        int t = (tid >= off) ? tmp[tid - off] : 0;
        __syncthreads();
        tmp[tid] += t;
        __syncthreads();
    }
    if (i < n_nodes) d_rowstart[i] = tmp[tid] - v;
    if (tid == SCAN_BLK - 1) d_blocksum[blockIdx.x] = tmp[tid];
}
__global__ void scan2_kernel(int n_blocks) {
    __shared__ int tmp[128];
    int tid = threadIdx.x;
    int v   = (tid < n_blocks) ? d_blocksum[tid] : 0;
    tmp[tid] = v;
    __syncthreads();
#pragma unroll
    for (int off = 1; off < 128; off <<= 1) {
        int t = (tid >= off) ? tmp[tid - off] : 0;
        __syncthreads();
        tmp[tid] += t;
        __syncthreads();
    }
    if (tid < n_blocks) d_blocksum[tid] = tmp[tid] - v;
}
__global__ void scan3_kernel(int n_nodes, int n_edges) {
    int i = blockIdx.x * blockDim.x + threadIdx.x;
    if (i < n_nodes) {
        int g = d_rowstart[i] + d_blocksum[i / SCAN_BLK];
        d_rowstart[i] = g;
        d_cursor[i]   = g;
    }
    if (i == 0) d_rowstart[n_nodes] = n_edges;
}
__global__ void reorder_kernel(const int* __restrict__ esrc,
                               const int* __restrict__ edst,
                               const float* __restrict__ eval_, int n_edges) {
    int e = blockIdx.x * blockDim.x + threadIdx.x;
    if (e >= n_edges) return;
    int pos = atomicAdd(&d_cursor[edst[e]], 1);
    unsigned long long pk = (unsigned long long)(unsigned)esrc[e]
                          | ((unsigned long long)__float_as_uint(eval_[e]) << 32);
    d_edgepack[pos] = pk;
}

// ---------------------------------------------------------------------------
// HMMA GEMM v2: out[:, 0:256] = X @ W via split-bf16 (3 terms).
// Block: 128 rows x 256 cols, 8 warps (2 m x 4 n), warp tile 64x64.
// K: 8 chunks of 32, cp.async double-buffered (96KB dynamic smem).
// Buffer layout per buf (48KB): Ahi@0(8K) Alo@8K Bhi@16K(16K) Blo@32K.
// ---------------------------------------------------------------------------
#define GBUF 49152
#define SM_GEMM_TOTAL (2 * GBUF)

__global__ __launch_bounds__(256, 1)
void gemm_mma_kernel(float* __restrict__ out, int n_rows) {
    extern __shared__ char sm[];
    const uint32_t smb = smem_u32(sm);

    const int tid  = threadIdx.x;
    const int wid  = tid >> 5;
    const int lane = tid & 31;
    const int wm   = wid >> 2;          // 0..1 -> 64-row half
    const int wn   = wid & 3;           // 0..3 -> 64-col quarter
    const int rowBase = blockIdx.x * 128;

    // prefetch chunk kc into buffer b
    auto prefetch = [&](int kc, int b) {
        const int kc0 = kc * 32;
        const uint32_t base = smb + b * GBUF;
#pragma unroll
        for (int p = 0; p < 2; p++) {              // A: 512 16B units hi, 512 lo
            int u = tid + p * 256;
            int r = u >> 2, c = u & 3;
            int gr = rowBase + r; if (gr >= n_rows) gr = n_rows - 1;
            size_t gp = (size_t)gr * N_FEAT + kc0 + c * 8;
            uint32_t off = TOFF(r, c);
            CP_ASYNC16(base + off,        d_xhi + gp);
            CP_ASYNC16(base + 8192 + off, d_xlo + gp);
        }
#pragma unroll
        for (int p = 0; p < 4; p++) {              // B: 1024 units hi, 1024 lo
            int u = tid + p * 256;
            int r = u >> 2, c = u & 3;
            size_t gp = (size_t)r * N_FEAT + kc0 + c * 8;
            uint32_t off = TOFF(r, c);
            CP_ASYNC16(base + 16384 + off, d_wthi + gp);
            CP_ASYNC16(base + 32768 + off, d_wtlo + gp);
        }
    };

    float acc[4][8][4];
#pragma unroll
    for (int mi = 0; mi < 4; mi++)
#pragma unroll
        for (int j = 0; j < 8; j++)
#pragma unroll
            for (int q = 0; q < 4; q++) acc[mi][j][q] = 0.f;

    prefetch(0, 0);
    CP_COMMIT();

    for (int kc = 0; kc < 8; kc++) {
        const int b = kc & 1;
        if (kc + 1 < 8) {
            prefetch(kc + 1, b ^ 1);
            CP_COMMIT();
            CP_WAIT(1);
        } else {
            CP_WAIT(0);
        }
        __syncthreads();

        const uint32_t base = smb + b * GBUF;
#pragma unroll
        for (int ks = 0; ks < 2; ks++) {
            uint32_t ahi[4][4], alo[4][4];
#pragma unroll
            for (int mi = 0; mi < 4; mi++) {
                int r = wm * 64 + mi * 16 + (lane & 15);
                int c = ks * 2 + (lane >> 4);
                uint32_t addr = base + TOFF(r, c);
                ldsm_x4(ahi[mi], addr);
                ldsm_x4(alo[mi], addr + 8192);
            }
#pragma unroll
            for (int nj = 0; nj < 4; nj++) {
                int r = wn * 64 + nj * 16 + (lane & 7) + ((lane >> 4) << 3);
                int c = ks * 2 + ((lane >> 3) & 1);
                uint32_t addr = base + 16384 + TOFF(r, c);
                uint32_t bhi[4], blo[4];
                ldsm_x4(bhi, addr);
                ldsm_x4(blo, addr + 16384);
#pragma unroll
                for (int mi = 0; mi < 4; mi++) {
#pragma unroll
                    for (int sub = 0; sub < 2; sub++) {
                        float* c4 = acc[mi][nj * 2 + sub];
                        mma_bf16(c4, ahi[mi], bhi + sub * 2);
                        mma_bf16(c4, ahi[mi], blo + sub * 2);
                        mma_bf16(c4, alo[mi], bhi + sub * 2);
                    }
                }
            }
        }
        __syncthreads();
    }

    // Epilogue: c-frag {c0,c1} row=l/4 col=2*(l%4); {c2,c3} row+8.
#pragma unroll
    for (int mi = 0; mi < 4; mi++) {
        int r0 = rowBase + wm * 64 + mi * 16 + (lane >> 2);
        int r1 = r0 + 8;
#pragma unroll
        for (int j = 0; j < 8; j++) {
            int col = wn * 64 + j * 8 + (lane & 3) * 2;
            if (r0 < n_rows)
                *reinterpret_cast<float2*>(out + (size_t)r0 * OUT_STRIDE + col) =
                    make_float2(acc[mi][j][0], acc[mi][j][1]);
            if (r1 < n_rows)
                *reinterpret_cast<float2*>(out + (size_t)r1 * OUT_STRIDE + col) =
                    make_float2(acc[mi][j][2], acc[mi][j][3]);
        }
    }
}

// ---------------------------------------------------------------------------
// Per-dst accumulate: one warp per node, no atomics, packed edge reads.
// ---------------------------------------------------------------------------
__global__ __launch_bounds__(256)
void accumulate_kernel(float* __restrict__ out, int n_nodes) {
    int w    = (blockIdx.x * blockDim.x + threadIdx.x) >> 5;
    int lane = threadIdx.x & 31;
    if (w >= n_nodes) return;

    int beg = d_rowstart[w];
    int end = d_rowstart[w + 1];

    float acc[8];
#pragma unroll
    for (int i = 0; i < 8; i++) acc[i] = 0.f;

    int i = beg;
    for (; i + 1 < end; i += 2) {
        unsigned long long p0 = __ldg(&d_edgepack[i]);
        unsigned long long p1 = __ldg(&d_edgepack[i + 1]);
        int   s0 = (int)(unsigned)p0;       float v0 = __uint_as_float((unsigned)(p0 >> 32));
        int   s1 = (int)(unsigned)p1;       float v1 = __uint_as_float((unsigned)(p1 >> 32));
        const float4* q0 = reinterpret_cast<const float4*>(out + (size_t)s0 * OUT_STRIDE + lane * 8);
        const float4* q1 = reinterpret_cast<const float4*>(out + (size_t)s1 * OUT_STRIDE + lane * 8);
        float4 a0 = __ldg(q0), b0 = __ldg(q0 + 1);
        float4 a1 = __ldg(q1), b1 = __ldg(q1 + 1);
        acc[0] += v0 * a0.x; acc[1] += v0 * a0.y; acc[2] += v0 * a0.z; acc[3] += v0 * a0.w;
        acc[4] += v0 * b0.x; acc[5] += v0 * b0.y; acc[6] += v0 * b0.z; acc[7] += v0 * b0.w;
        acc[0] += v1 * a1.x; acc[1] += v1 * a1.y; acc[2] += v1 * a1.z; acc[3] += v1 * a1.w;
        acc[4] += v1 * b1.x; acc[5] += v1 * b1.y; acc[6] += v1 * b1.z; acc[7] += v1 * b1.w;
    }
    if (i < end) {
        unsigned long long p0 = __ldg(&d_edgepack[i]);
        int   s0 = (int)(unsigned)p0;       float v0 = __uint_as_float((unsigned)(p0 >> 32));
        const float4* q0 = reinterpret_cast<const float4*>(out + (size_t)s0 * OUT_STRIDE + lane * 8);
        float4 a0 = __ldg(q0), b0 = __ldg(q0 + 1);
        acc[0] += v0 * a0.x; acc[1] += v0 * a0.y; acc[2] += v0 * a0.z; acc[3] += v0 * a0.w;
        acc[4] += v0 * b0.x; acc[5] += v0 * b0.y; acc[6] += v0 * b0.z; acc[7] += v0 * b0.w;
    }

    float* o = out + (size_t)w * OUT_STRIDE + N_FEAT + lane * 8;
    *reinterpret_cast<float4*>(o)     = make_float4(acc[0], acc[1], acc[2], acc[3]);
    *reinterpret_cast<float4*>(o + 4) = make_float4(acc[4], acc[5], acc[6], acc[7]);
}

// ---------------------------------------------------------------------------
// Launch
// ---------------------------------------------------------------------------
extern "C" void kernel_launch(void* const* d_in, const int* in_sizes, int n_in,
                              void* d_out, int out_size) {
    const float* input_   = (const float*)d_in[0];
    const int*   edge_src = (const int*)d_in[1];
    const int*   edge_dst = (const int*)d_in[2];
    const float* edge_val = (const float*)d_in[3];
    const float* weight   = (const float*)d_in[4];
    float*       out      = (float*)d_out;

    const int n_nodes = in_sizes[0] / N_FEAT;
    const int n_edges = in_sizes[1];

    const int eb = (n_edges + 255) / 256;
    const int nb = (n_nodes + 255) / 256;
    const int scan_blocks = (n_nodes + SCAN_BLK - 1) / SCAN_BLK;

    // split-bf16 operand prep
    int total4 = n_nodes * (N_FEAT / 4);
    convert_x_kernel<<<(total4 + 255) / 256, 256>>>(input_, total4);
    convert_w_kernel<<<(N_FEAT * N_FEAT + 255) / 256, 256>>>(weight);

    // CSR build
    zero_count_kernel<<<nb, 256>>>(n_nodes);
    hist_kernel<<<eb, 256>>>(edge_dst, n_edges);
    scan1_kernel<<<scan_blocks, SCAN_BLK>>>(n_nodes);
    scan2_kernel<<<1, 128>>>(scan_blocks);
    scan3_kernel<<<nb, 256>>>(n_nodes, n_edges);
    reorder_kernel<<<eb, 256>>>(edge_src, edge_dst, edge_val, n_edges);

    // ft_input = X @ W  (pipelined HMMA split-bf16)  -> out[:, 0:256]
    cudaFuncSetAttribute(gemm_mma_kernel,
                         cudaFuncAttributeMaxDynamicSharedMemorySize, SM_GEMM_TOTAL);
    int gemm_blocks = (n_nodes + 127) / 128;
    gemm_mma_kernel<<<gemm_blocks, 256, SM_GEMM_TOTAL>>>(out, n_nodes);

    // ft_neighbor = A @ ft_input -> out[:, 256:512]
    int acc_blocks = (n_nodes * 32 + 255) / 256;
    accumulate_kernel<<<acc_blocks, 256>>>(out, n_nodes);
}

// round 7
// speedup vs baseline: 1.9465x; 1.3015x over previous
#include <cuda_runtime.h>
#include <cuda_bf16.h>
#include <cuda_fp16.h>
#include <cstdint>

#define N_FEAT 256          // IN_F == OUT_F == 256
#define OUT_STRIDE 512      // concat([ft_input, ft_neighbor], axis=1)

#define MAX_NODES 100000
#define MAX_EDGES 3200000
#define SCAN_BLK 1024
#define MAX_SCAN_BLOCKS ((MAX_NODES + SCAN_BLK - 1) / SCAN_BLK)   // 98

// ---------------------------------------------------------------------------
// Scratch (device globals)
// ---------------------------------------------------------------------------
__device__ int                d_cursor[MAX_NODES];
__device__ int                d_rowstart[MAX_NODES + 1];
__device__ int                d_blocksum[MAX_SCAN_BLOCKS];
__device__ unsigned long long d_edgepack[MAX_EDGES];   // src | (valbits << 32)
// split-bf16 operands
__device__ __nv_bfloat16 d_xhi[(size_t)MAX_NODES * N_FEAT];
__device__ __nv_bfloat16 d_xlo[(size_t)MAX_NODES * N_FEAT];
__device__ __nv_bfloat16 d_wthi[N_FEAT * N_FEAT];   // W^T : [n][k]
__device__ __nv_bfloat16 d_wtlo[N_FEAT * N_FEAT];
// fp16 copy of ft_input for the gather phase (51.2 MB, L2-resident)
__device__ __half d_fthalf[(size_t)MAX_NODES * N_FEAT];

// ---------------------------------------------------------------------------
// PTX helpers (baseline PTX only — valid on compute_103)
// ---------------------------------------------------------------------------
__device__ __forceinline__ uint32_t smem_u32(const void* p) {
    uint32_t a;
    asm("{ .reg .u64 t; cvta.to.shared.u64 t, %1; cvt.u32.u64 %0, t; }"
        : "=r"(a) : "l"(p));
    return a;
}
__device__ __forceinline__ void ldsm_x4(uint32_t* r, uint32_t addr) {
    asm volatile("ldmatrix.sync.aligned.m8n8.x4.shared.b16 {%0,%1,%2,%3}, [%4];"
                 : "=r"(r[0]), "=r"(r[1]), "=r"(r[2]), "=r"(r[3]) : "r"(addr));
}
__device__ __forceinline__ void mma_bf16(float* c, const uint32_t* a, const uint32_t* b) {
    asm volatile(
        "mma.sync.aligned.m16n8k16.row.col.f32.bf16.bf16.f32 "
        "{%0,%1,%2,%3}, {%4,%5,%6,%7}, {%8,%9}, {%0,%1,%2,%3};"
        : "+f"(c[0]), "+f"(c[1]), "+f"(c[2]), "+f"(c[3])
        : "r"(a[0]), "r"(a[1]), "r"(a[2]), "r"(a[3]), "r"(b[0]), "r"(b[1]));
}
#define CP_ASYNC16(dst, src) \
    asm volatile("cp.async.cg.shared.global [%0], [%1], 16;" :: "r"(dst), "l"(src))
#define CP_COMMIT() asm volatile("cp.async.commit_group;" ::: "memory")
#define CP_WAIT(n)  asm volatile("cp.async.wait_group %0;" :: "n"(n) : "memory")

// XOR swizzle on 16B units (4 units per 64B row): conflict-free STS + LDSM.
#define SWU(r, c) ((c) ^ (((r) >> 1) & 3))
#define TOFF(r, c) ((uint32_t)(((r) * 4 + SWU(r, c)) * 16))

// ---------------------------------------------------------------------------
// Conversion kernels: f32 -> (hi, lo) bf16 split
// ---------------------------------------------------------------------------
__global__ void convert_x_kernel(const float* __restrict__ x, int total4) {
    int i = blockIdx.x * blockDim.x + threadIdx.x;
    if (i >= total4) return;
    float4 v = reinterpret_cast<const float4*>(x)[i];
    __nv_bfloat16 h0 = __float2bfloat16(v.x), h1 = __float2bfloat16(v.y);
    __nv_bfloat16 h2 = __float2bfloat16(v.z), h3 = __float2bfloat16(v.w);
    __nv_bfloat16 l0 = __float2bfloat16(v.x - __bfloat162float(h0));
    __nv_bfloat16 l1 = __float2bfloat16(v.y - __bfloat162float(h1));
    __nv_bfloat16 l2 = __float2bfloat16(v.z - __bfloat162float(h2));
    __nv_bfloat16 l3 = __float2bfloat16(v.w - __bfloat162float(h3));
    reinterpret_cast<__nv_bfloat162*>(d_xhi)[i * 2]     = __nv_bfloat162(h0, h1);
    reinterpret_cast<__nv_bfloat162*>(d_xhi)[i * 2 + 1] = __nv_bfloat162(h2, h3);
    reinterpret_cast<__nv_bfloat162*>(d_xlo)[i * 2]     = __nv_bfloat162(l0, l1);
    reinterpret_cast<__nv_bfloat162*>(d_xlo)[i * 2 + 1] = __nv_bfloat162(l2, l3);
}

__global__ void convert_w_kernel(const float* __restrict__ w) {
    int idx = blockIdx.x * blockDim.x + threadIdx.x;   // over 256*256
    if (idx >= N_FEAT * N_FEAT) return;
    int n = idx >> 8, k = idx & 255;
    float v = w[k * N_FEAT + n];                        // transpose -> [n][k]
    __nv_bfloat16 h = __float2bfloat16(v);
    __nv_bfloat16 l = __float2bfloat16(v - __bfloat162float(h));
    d_wthi[n * N_FEAT + k] = h;
    d_wtlo[n * N_FEAT + k] = l;
}

// ---------------------------------------------------------------------------
// CSR build
// ---------------------------------------------------------------------------
__global__ void zero_count_kernel(int n_nodes) {
    int i = blockIdx.x * blockDim.x + threadIdx.x;
    if (i < n_nodes) d_cursor[i] = 0;
}
__global__ void hist_kernel(const int* __restrict__ edst, int n_edges) {
    int e = blockIdx.x * blockDim.x + threadIdx.x;
    if (e < n_edges) atomicAdd(&d_cursor[edst[e]], 1);
}
__global__ __launch_bounds__(SCAN_BLK)
void scan1_kernel(int n_nodes) {
    __shared__ int tmp[SCAN_BLK];
    int tid = threadIdx.x;
    int i   = blockIdx.x * SCAN_BLK + tid;
    int v   = (i < n_nodes) ? d_cursor[i] : 0;
    tmp[tid] = v;
    __syncthreads();
#pragma unroll
    for (int off = 1; off < SCAN_BLK; off <<= 1) {
        int t = (tid >= off) ? tmp[tid - off] : 0;
        __syncthreads();
        tmp[tid] += t;
        __syncthreads();
    }
    if (i < n_nodes) d_rowstart[i] = tmp[tid] - v;
    if (tid == SCAN_BLK - 1) d_blocksum[blockIdx.x] = tmp[tid];
}
__global__ void scan2_kernel(int n_blocks) {
    __shared__ int tmp[128];
    int tid = threadIdx.x;
    int v   = (tid < n_blocks) ? d_blocksum[tid] : 0;
    tmp[tid] = v;
    __syncthreads();
#pragma unroll
    for (int off = 1; off < 128; off <<= 1) {
        int t = (tid >= off) ? tmp[tid - off] : 0;
        __syncthreads();
        tmp[tid] += t;
        __syncthreads();
    }
    if (tid < n_blocks) d_blocksum[tid] = tmp[tid] - v;
}
__global__ void scan3_kernel(int n_nodes, int n_edges) {
    int i = blockIdx.x * blockDim.x + threadIdx.x;
    if (i < n_nodes) {
        int g = d_rowstart[i] + d_blocksum[i / SCAN_BLK];
        d_rowstart[i] = g;
        d_cursor[i]   = g;
    }
    if (i == 0) d_rowstart[n_nodes] = n_edges;
}
__global__ void reorder_kernel(const int* __restrict__ esrc,
                               const int* __restrict__ edst,
                               const float* __restrict__ eval_, int n_edges) {
    int e = blockIdx.x * blockDim.x + threadIdx.x;
    if (e >= n_edges) return;
    int pos = atomicAdd(&d_cursor[edst[e]], 1);
    unsigned long long pk = (unsigned long long)(unsigned)esrc[e]
                          | ((unsigned long long)__float_as_uint(eval_[e]) << 32);
    d_edgepack[pos] = pk;
}

// ---------------------------------------------------------------------------
// HMMA GEMM v2: out[:, 0:256] = X @ W via split-bf16 (3 terms).
// Block: 128 rows x 256 cols, 8 warps (2 m x 4 n), warp tile 64x64.
// K: 8 chunks of 32, cp.async double-buffered. Epilogue also stores fp16
// copy of ft_input for the gather phase.
// ---------------------------------------------------------------------------
#define GBUF 49152
#define SM_GEMM_TOTAL (2 * GBUF)

__global__ __launch_bounds__(256, 1)
void gemm_mma_kernel(float* __restrict__ out, int n_rows) {
    extern __shared__ char sm[];
    const uint32_t smb = smem_u32(sm);

    const int tid  = threadIdx.x;
    const int wid  = tid >> 5;
    const int lane = tid & 31;
    const int wm   = wid >> 2;          // 0..1 -> 64-row half
    const int wn   = wid & 3;           // 0..3 -> 64-col quarter
    const int rowBase = blockIdx.x * 128;

    auto prefetch = [&](int kc, int b) {
        const int kc0 = kc * 32;
        const uint32_t base = smb + b * GBUF;
#pragma unroll
        for (int p = 0; p < 2; p++) {              // A: 512 16B units hi, 512 lo
            int u = tid + p * 256;
            int r = u >> 2, c = u & 3;
            int gr = rowBase + r; if (gr >= n_rows) gr = n_rows - 1;
            size_t gp = (size_t)gr * N_FEAT + kc0 + c * 8;
            uint32_t off = TOFF(r, c);
            CP_ASYNC16(base + off,        d_xhi + gp);
            CP_ASYNC16(base + 8192 + off, d_xlo + gp);
        }
#pragma unroll
        for (int p = 0; p < 4; p++) {              // B: 1024 units hi, 1024 lo
            int u = tid + p * 256;
            int r = u >> 2, c = u & 3;
            size_t gp = (size_t)r * N_FEAT + kc0 + c * 8;
            uint32_t off = TOFF(r, c);
            CP_ASYNC16(base + 16384 + off, d_wthi + gp);
            CP_ASYNC16(base + 32768 + off, d_wtlo + gp);
        }
    };

    float acc[4][8][4];
#pragma unroll
    for (int mi = 0; mi < 4; mi++)
#pragma unroll
        for (int j = 0; j < 8; j++)
#pragma unroll
            for (int q = 0; q < 4; q++) acc[mi][j][q] = 0.f;

    prefetch(0, 0);
    CP_COMMIT();

    for (int kc = 0; kc < 8; kc++) {
        const int b = kc & 1;
        if (kc + 1 < 8) {
            prefetch(kc + 1, b ^ 1);
            CP_COMMIT();
            CP_WAIT(1);
        } else {
            CP_WAIT(0);
        }
        __syncthreads();

        const uint32_t base = smb + b * GBUF;
#pragma unroll
        for (int ks = 0; ks < 2; ks++) {
            uint32_t ahi[4][4], alo[4][4];
#pragma unroll
            for (int mi = 0; mi < 4; mi++) {
                int r = wm * 64 + mi * 16 + (lane & 15);
                int c = ks * 2 + (lane >> 4);
                uint32_t addr = base + TOFF(r, c);
                ldsm_x4(ahi[mi], addr);
                ldsm_x4(alo[mi], addr + 8192);
            }
#pragma unroll
            for (int nj = 0; nj < 4; nj++) {
                int r = wn * 64 + nj * 16 + (lane & 7) + ((lane >> 4) << 3);
                int c = ks * 2 + ((lane >> 3) & 1);
                uint32_t addr = base + 16384 + TOFF(r, c);
                uint32_t bhi[4], blo[4];
                ldsm_x4(bhi, addr);
                ldsm_x4(blo, addr + 16384);
#pragma unroll
                for (int mi = 0; mi < 4; mi++) {
#pragma unroll
                    for (int sub = 0; sub < 2; sub++) {
                        float* c4 = acc[mi][nj * 2 + sub];
                        mma_bf16(c4, ahi[mi], bhi + sub * 2);
                        mma_bf16(c4, ahi[mi], blo + sub * 2);
                        mma_bf16(c4, alo[mi], bhi + sub * 2);
                    }
                }
            }
        }
        __syncthreads();
    }

    // Epilogue: c-frag {c0,c1} row=l/4 col=2*(l%4); {c2,c3} row+8.
    // Also store fp16 copy for gather phase.
#pragma unroll
    for (int mi = 0; mi < 4; mi++) {
        int r0 = rowBase + wm * 64 + mi * 16 + (lane >> 2);
        int r1 = r0 + 8;
#pragma unroll
        for (int j = 0; j < 8; j++) {
            int col = wn * 64 + j * 8 + (lane & 3) * 2;
            if (r0 < n_rows) {
                *reinterpret_cast<float2*>(out + (size_t)r0 * OUT_STRIDE + col) =
                    make_float2(acc[mi][j][0], acc[mi][j][1]);
                *reinterpret_cast<__half2*>(d_fthalf + (size_t)r0 * N_FEAT + col) =
                    __floats2half2_rn(acc[mi][j][0], acc[mi][j][1]);
            }
            if (r1 < n_rows) {
                *reinterpret_cast<float2*>(out + (size_t)r1 * OUT_STRIDE + col) =
                    make_float2(acc[mi][j][2], acc[mi][j][3]);
                *reinterpret_cast<__half2*>(d_fthalf + (size_t)r1 * N_FEAT + col) =
                    __floats2half2_rn(acc[mi][j][2], acc[mi][j][3]);
            }
        }
    }
}

// ---------------------------------------------------------------------------
// Per-dst accumulate: one warp per node, no atomics, fp16 gathers.
// Each lane reads 8 halves (16B) per edge; accumulates in fp32.
// ---------------------------------------------------------------------------
__global__ __launch_bounds__(256)
void accumulate_kernel(float* __restrict__ out, int n_nodes) {
    int w    = (blockIdx.x * blockDim.x + threadIdx.x) >> 5;
    int lane = threadIdx.x & 31;
    if (w >= n_nodes) return;

    int beg = d_rowstart[w];
    int end = d_rowstart[w + 1];

    float acc[8];
#pragma unroll
    for (int i = 0; i < 8; i++) acc[i] = 0.f;

    auto accum_one = [&](unsigned long long pk) {
        int   s = (int)(unsigned)pk;
        float v = __uint_as_float((unsigned)(pk >> 32));
        uint4 u = __ldg(reinterpret_cast<const uint4*>(
            d_fthalf + (size_t)s * N_FEAT + lane * 8));
        const __half2* h = reinterpret_cast<const __half2*>(&u);
#pragma unroll
        for (int q = 0; q < 4; q++) {
            float2 f = __half22float2(h[q]);
            acc[q * 2]     += v * f.x;
            acc[q * 2 + 1] += v * f.y;
        }
    };

    int i = beg;
    for (; i + 1 < end; i += 2) {
        unsigned long long p0 = __ldg(&d_edgepack[i]);
        unsigned long long p1 = __ldg(&d_edgepack[i + 1]);
        accum_one(p0);
        accum_one(p1);
    }
    if (i < end) accum_one(__ldg(&d_edgepack[i]));

    // acc[q*2], acc[q*2+1] correspond to cols lane*8 + q*2 .. — contiguous 8
    float* o = out + (size_t)w * OUT_STRIDE + N_FEAT + lane * 8;
    *reinterpret_cast<float4*>(o)     = make_float4(acc[0], acc[1], acc[2], acc[3]);
    *reinterpret_cast<float4*>(o + 4) = make_float4(acc[4], acc[5], acc[6], acc[7]);
}

// ---------------------------------------------------------------------------
// Launch
// ---------------------------------------------------------------------------
extern "C" void kernel_launch(void* const* d_in, const int* in_sizes, int n_in,
                              void* d_out, int out_size) {
    const float* input_   = (const float*)d_in[0];
    const int*   edge_src = (const int*)d_in[1];
    const int*   edge_dst = (const int*)d_in[2];
    const float* edge_val = (const float*)d_in[3];
    const float* weight   = (const float*)d_in[4];
    float*       out      = (float*)d_out;

    const int n_nodes = in_sizes[0] / N_FEAT;
    const int n_edges = in_sizes[1];

    const int eb = (n_edges + 255) / 256;
    const int nb = (n_nodes + 255) / 256;
    const int scan_blocks = (n_nodes + SCAN_BLK - 1) / SCAN_BLK;

    // split-bf16 operand prep
    int total4 = n_nodes * (N_FEAT / 4);
    convert_x_kernel<<<(total4 + 255) / 256, 256>>>(input_, total4);
    convert_w_kernel<<<(N_FEAT * N_FEAT + 255) / 256, 256>>>(weight);

    // CSR build
    zero_count_kernel<<<nb, 256>>>(n_nodes);
    hist_kernel<<<eb, 256>>>(edge_dst, n_edges);
    scan1_kernel<<<scan_blocks, SCAN_BLK>>>(n_nodes);
    scan2_kernel<<<1, 128>>>(scan_blocks);
    scan3_kernel<<<nb, 256>>>(n_nodes, n_edges);
    reorder_kernel<<<eb, 256>>>(edge_src, edge_dst, edge_val, n_edges);

    // ft_input = X @ W  (pipelined HMMA split-bf16)  -> out[:, 0:256] + fp16 copy
    cudaFuncSetAttribute(gemm_mma_kernel,
                         cudaFuncAttributeMaxDynamicSharedMemorySize, SM_GEMM_TOTAL);
    int gemm_blocks = (n_nodes + 127) / 128;
    gemm_mma_kernel<<<gemm_blocks, 256, SM_GEMM_TOTAL>>>(out, n_nodes);

    // ft_neighbor = A @ ft_input -> out[:, 256:512]  (fp16 gathers)
    int acc_blocks = (n_nodes * 32 + 255) / 256;
    accumulate_kernel<<<acc_blocks, 256>>>(out, n_nodes);
}

// round 8
// speedup vs baseline: 1.9984x; 1.0267x over previous
#include <cuda_runtime.h>
#include <cuda_bf16.h>
#include <cuda_fp16.h>
#include <cstdint>

#define N_FEAT 256          // IN_F == OUT_F == 256
#define OUT_STRIDE 512      // concat([ft_input, ft_neighbor], axis=1)

#define MAX_NODES 100000
#define MAX_EDGES 3200000
#define SCAN_BLK 1024
#define MAX_SCAN_BLOCKS ((MAX_NODES + SCAN_BLK - 1) / SCAN_BLK)   // 98

// ---------------------------------------------------------------------------
// Scratch (device globals)
// ---------------------------------------------------------------------------
__device__ int                d_cursor[MAX_NODES];
__device__ int                d_rowstart[MAX_NODES + 1];
__device__ int                d_blocksum[MAX_SCAN_BLOCKS];
__device__ unsigned long long d_edgepack[MAX_EDGES];   // src | (valbits << 32)
// fp16 GEMM operands
__device__ __half d_xh[(size_t)MAX_NODES * N_FEAT];    // X in fp16
__device__ __half d_wth[N_FEAT * N_FEAT];              // W^T : [n][k] fp16
// fp16 copy of ft_input for the gather phase (51.2 MB, L2-resident)
__device__ __half d_fthalf[(size_t)MAX_NODES * N_FEAT];

// ---------------------------------------------------------------------------
// PTX helpers (baseline PTX only — valid on compute_103)
// ---------------------------------------------------------------------------
__device__ __forceinline__ uint32_t smem_u32(const void* p) {
    uint32_t a;
    asm("{ .reg .u64 t; cvta.to.shared.u64 t, %1; cvt.u32.u64 %0, t; }"
        : "=r"(a) : "l"(p));
    return a;
}
__device__ __forceinline__ void ldsm_x4(uint32_t* r, uint32_t addr) {
    asm volatile("ldmatrix.sync.aligned.m8n8.x4.shared.b16 {%0,%1,%2,%3}, [%4];"
                 : "=r"(r[0]), "=r"(r[1]), "=r"(r[2]), "=r"(r[3]) : "r"(addr));
}
__device__ __forceinline__ void mma_f16(float* c, const uint32_t* a, const uint32_t* b) {
    asm volatile(
        "mma.sync.aligned.m16n8k16.row.col.f32.f16.f16.f32 "
        "{%0,%1,%2,%3}, {%4,%5,%6,%7}, {%8,%9}, {%0,%1,%2,%3};"
        : "+f"(c[0]), "+f"(c[1]), "+f"(c[2]), "+f"(c[3])
        : "r"(a[0]), "r"(a[1]), "r"(a[2]), "r"(a[3]), "r"(b[0]), "r"(b[1]));
}
#define CP_ASYNC16(dst, src) \
    asm volatile("cp.async.cg.shared.global [%0], [%1], 16;" :: "r"(dst), "l"(src))
#define CP_COMMIT() asm volatile("cp.async.commit_group;" ::: "memory")
#define CP_WAIT(n)  asm volatile("cp.async.wait_group %0;" :: "n"(n) : "memory")

// XOR swizzle on 16B units (4 units per 64B row): conflict-free STS + LDSM.
#define SWU(r, c) ((c) ^ (((r) >> 1) & 3))
#define TOFF(r, c) ((uint32_t)(((r) * 4 + SWU(r, c)) * 16))

// ---------------------------------------------------------------------------
// Conversion kernels: f32 -> fp16
// ---------------------------------------------------------------------------
__global__ void convert_x_kernel(const float* __restrict__ x, int total4) {
    int i = blockIdx.x * blockDim.x + threadIdx.x;
    if (i >= total4) return;
    float4 v = reinterpret_cast<const float4*>(x)[i];
    reinterpret_cast<__half2*>(d_xh)[i * 2]     = __floats2half2_rn(v.x, v.y);
    reinterpret_cast<__half2*>(d_xh)[i * 2 + 1] = __floats2half2_rn(v.z, v.w);
}

__global__ void convert_w_kernel(const float* __restrict__ w) {
    int idx = blockIdx.x * blockDim.x + threadIdx.x;   // over 256*256
    if (idx >= N_FEAT * N_FEAT) return;
    int n = idx >> 8, k = idx & 255;
    d_wth[n * N_FEAT + k] = __float2half_rn(w[k * N_FEAT + n]);   // transpose
}

// ---------------------------------------------------------------------------
// CSR build
// ---------------------------------------------------------------------------
__global__ void zero_count_kernel(int n_nodes) {
    int i = blockIdx.x * blockDim.x + threadIdx.x;
    if (i < n_nodes) d_cursor[i] = 0;
}
__global__ void hist_kernel(const int* __restrict__ edst, int n_edges) {
    int e = blockIdx.x * blockDim.x + threadIdx.x;
    if (e < n_edges) atomicAdd(&d_cursor[edst[e]], 1);
}
__global__ __launch_bounds__(SCAN_BLK)
void scan1_kernel(int n_nodes) {
    __shared__ int tmp[SCAN_BLK];
    int tid = threadIdx.x;
    int i   = blockIdx.x * SCAN_BLK + tid;
    int v   = (i < n_nodes) ? d_cursor[i] : 0;
    tmp[tid] = v;
    __syncthreads();
#pragma unroll
    for (int off = 1; off < SCAN_BLK; off <<= 1) {
        int t = (tid >= off) ? tmp[tid - off] : 0;
        __syncthreads();
        tmp[tid] += t;
        __syncthreads();
    }
    if (i < n_nodes) d_rowstart[i] = tmp[tid] - v;
    if (tid == SCAN_BLK - 1) d_blocksum[blockIdx.x] = tmp[tid];
}
__global__ void scan2_kernel(int n_blocks) {
    __shared__ int tmp[128];
    int tid = threadIdx.x;
    int v   = (tid < n_blocks) ? d_blocksum[tid] : 0;
    tmp[tid] = v;
    __syncthreads();
#pragma unroll
    for (int off = 1; off < 128; off <<= 1) {
        int t = (tid >= off) ? tmp[tid - off] : 0;
        __syncthreads();
        tmp[tid] += t;
        __syncthreads();
    }
    if (tid < n_blocks) d_blocksum[tid] = tmp[tid] - v;
}
__global__ void scan3_kernel(int n_nodes, int n_edges) {
    int i = blockIdx.x * blockDim.x + threadIdx.x;
    if (i < n_nodes) {
        int g = d_rowstart[i] + d_blocksum[i / SCAN_BLK];
        d_rowstart[i] = g;
        d_cursor[i]   = g;
    }
    if (i == 0) d_rowstart[n_nodes] = n_edges;
}
__global__ void reorder_kernel(const int* __restrict__ esrc,
                               const int* __restrict__ edst,
                               const float* __restrict__ eval_, int n_edges) {
    int e = blockIdx.x * blockDim.x + threadIdx.x;
    if (e >= n_edges) return;
    int pos = atomicAdd(&d_cursor[edst[e]], 1);
    unsigned long long pk = (unsigned long long)(unsigned)esrc[e]
                          | ((unsigned long long)__float_as_uint(eval_[e]) << 32);
    d_edgepack[pos] = pk;
}

// ---------------------------------------------------------------------------
// fp16 HMMA GEMM: out[:, 0:256] = X @ W  (single term, fp32 accum).
// Block: 128 rows x 256 cols, 8 warps (2 m x 4 n), warp tile 64x64.
// K: 8 chunks of 32, cp.async double-buffered (48KB smem -> 2 CTAs/SM).
// Buffer layout per buf (24KB): A@0 (8KB), B@8K (16KB).
// ---------------------------------------------------------------------------
#define GBUF 24576
#define SM_GEMM_TOTAL (2 * GBUF)

__global__ __launch_bounds__(256, 2)
void gemm_mma_kernel(float* __restrict__ out, int n_rows) {
    extern __shared__ char sm[];
    const uint32_t smb = smem_u32(sm);

    const int tid  = threadIdx.x;
    const int wid  = tid >> 5;
    const int lane = tid & 31;
    const int wm   = wid >> 2;          // 0..1 -> 64-row half
    const int wn   = wid & 3;           // 0..3 -> 64-col quarter
    const int rowBase = blockIdx.x * 128;

    auto prefetch = [&](int kc, int b) {
        const int kc0 = kc * 32;
        const uint32_t base = smb + b * GBUF;
#pragma unroll
        for (int p = 0; p < 2; p++) {              // A: 512 16B units
            int u = tid + p * 256;
            int r = u >> 2, c = u & 3;
            int gr = rowBase + r; if (gr >= n_rows) gr = n_rows - 1;
            size_t gp = (size_t)gr * N_FEAT + kc0 + c * 8;
            CP_ASYNC16(base + TOFF(r, c), d_xh + gp);
        }
#pragma unroll
        for (int p = 0; p < 4; p++) {              // B: 1024 16B units
            int u = tid + p * 256;
            int r = u >> 2, c = u & 3;
            size_t gp = (size_t)r * N_FEAT + kc0 + c * 8;
            CP_ASYNC16(base + 8192 + TOFF(r, c), d_wth + gp);
        }
    };

    float acc[4][8][4];
#pragma unroll
    for (int mi = 0; mi < 4; mi++)
#pragma unroll
        for (int j = 0; j < 8; j++)
#pragma unroll
            for (int q = 0; q < 4; q++) acc[mi][j][q] = 0.f;

    prefetch(0, 0);
    CP_COMMIT();

    for (int kc = 0; kc < 8; kc++) {
        const int b = kc & 1;
        if (kc + 1 < 8) {
            prefetch(kc + 1, b ^ 1);
            CP_COMMIT();
            CP_WAIT(1);
        } else {
            CP_WAIT(0);
        }
        __syncthreads();

        const uint32_t base = smb + b * GBUF;
#pragma unroll
        for (int ks = 0; ks < 2; ks++) {
            uint32_t af[4][4];
#pragma unroll
            for (int mi = 0; mi < 4; mi++) {
                int r = wm * 64 + mi * 16 + (lane & 15);
                int c = ks * 2 + (lane >> 4);
                ldsm_x4(af[mi], base + TOFF(r, c));
            }
#pragma unroll
            for (int nj = 0; nj < 4; nj++) {
                int r = wn * 64 + nj * 16 + (lane & 7) + ((lane >> 4) << 3);
                int c = ks * 2 + ((lane >> 3) & 1);
                uint32_t bf[4];
                ldsm_x4(bf, base + 8192 + TOFF(r, c));
#pragma unroll
                for (int mi = 0; mi < 4; mi++) {
                    mma_f16(acc[mi][nj * 2],     af[mi], bf);
                    mma_f16(acc[mi][nj * 2 + 1], af[mi], bf + 2);
                }
            }
        }
        __syncthreads();
    }

    // Epilogue: c-frag {c0,c1} row=l/4 col=2*(l%4); {c2,c3} row+8.
    // Also store fp16 copy for gather phase.
#pragma unroll
    for (int mi = 0; mi < 4; mi++) {
        int r0 = rowBase + wm * 64 + mi * 16 + (lane >> 2);
        int r1 = r0 + 8;
#pragma unroll
        for (int j = 0; j < 8; j++) {
            int col = wn * 64 + j * 8 + (lane & 3) * 2;
            if (r0 < n_rows) {
                *reinterpret_cast<float2*>(out + (size_t)r0 * OUT_STRIDE + col) =
                    make_float2(acc[mi][j][0], acc[mi][j][1]);
                *reinterpret_cast<__half2*>(d_fthalf + (size_t)r0 * N_FEAT + col) =
                    __floats2half2_rn(acc[mi][j][0], acc[mi][j][1]);
            }
            if (r1 < n_rows) {
                *reinterpret_cast<float2*>(out + (size_t)r1 * OUT_STRIDE + col) =
                    make_float2(acc[mi][j][2], acc[mi][j][3]);
                *reinterpret_cast<__half2*>(d_fthalf + (size_t)r1 * N_FEAT + col) =
                    __floats2half2_rn(acc[mi][j][2], acc[mi][j][3]);
            }
        }
    }
}

// ---------------------------------------------------------------------------
// Per-dst accumulate: one warp per node, no atomics, fp16 gathers.
// ---------------------------------------------------------------------------
__global__ __launch_bounds__(256)
void accumulate_kernel(float* __restrict__ out, int n_nodes) {
    int w    = (blockIdx.x * blockDim.x + threadIdx.x) >> 5;
    int lane = threadIdx.x & 31;
    if (w >= n_nodes) return;

    int beg = d_rowstart[w];
    int end = d_rowstart[w + 1];

    float acc[8];
#pragma unroll
    for (int i = 0; i < 8; i++) acc[i] = 0.f;

    auto accum_one = [&](unsigned long long pk) {
        int   s = (int)(unsigned)pk;
        float v = __uint_as_float((unsigned)(pk >> 32));
        uint4 u = __ldg(reinterpret_cast<const uint4*>(
            d_fthalf + (size_t)s * N_FEAT + lane * 8));
        const __half2* h = reinterpret_cast<const __half2*>(&u);
#pragma unroll
        for (int q = 0; q < 4; q++) {
            float2 f = __half22float2(h[q]);
            acc[q * 2]     += v * f.x;
            acc[q * 2 + 1] += v * f.y;
        }
    };

    int i = beg;
    for (; i + 1 < end; i += 2) {
        unsigned long long p0 = __ldg(&d_edgepack[i]);
        unsigned long long p1 = __ldg(&d_edgepack[i + 1]);
        accum_one(p0);
        accum_one(p1);
    }
    if (i < end) accum_one(__ldg(&d_edgepack[i]));

    float* o = out + (size_t)w * OUT_STRIDE + N_FEAT + lane * 8;
    *reinterpret_cast<float4*>(o)     = make_float4(acc[0], acc[1], acc[2], acc[3]);
    *reinterpret_cast<float4*>(o + 4) = make_float4(acc[4], acc[5], acc[6], acc[7]);
}

// ---------------------------------------------------------------------------
// Launch
// ---------------------------------------------------------------------------
extern "C" void kernel_launch(void* const* d_in, const int* in_sizes, int n_in,
                              void* d_out, int out_size) {
    const float* input_   = (const float*)d_in[0];
    const int*   edge_src = (const int*)d_in[1];
    const int*   edge_dst = (const int*)d_in[2];
    const float* edge_val = (const float*)d_in[3];
    const float* weight   = (const float*)d_in[4];
    float*       out      = (float*)d_out;

    const int n_nodes = in_sizes[0] / N_FEAT;
    const int n_edges = in_sizes[1];

    const int eb = (n_edges + 255) / 256;
    const int nb = (n_nodes + 255) / 256;
    const int scan_blocks = (n_nodes + SCAN_BLK - 1) / SCAN_BLK;

    // fp16 operand prep
    int total4 = n_nodes * (N_FEAT / 4);
    convert_x_kernel<<<(total4 + 255) / 256, 256>>>(input_, total4);
    convert_w_kernel<<<(N_FEAT * N_FEAT + 255) / 256, 256>>>(weight);

    // CSR build
    zero_count_kernel<<<nb, 256>>>(n_nodes);
    hist_kernel<<<eb, 256>>>(edge_dst, n_edges);
    scan1_kernel<<<scan_blocks, SCAN_BLK>>>(n_nodes);
    scan2_kernel<<<1, 128>>>(scan_blocks);
    scan3_kernel<<<nb, 256>>>(n_nodes, n_edges);
    reorder_kernel<<<eb, 256>>>(edge_src, edge_dst, edge_val, n_edges);

    // ft_input = X @ W  (fp16 HMMA, fp32 accum)  -> out[:, 0:256] + fp16 copy
    cudaFuncSetAttribute(gemm_mma_kernel,
                         cudaFuncAttributeMaxDynamicSharedMemorySize, SM_GEMM_TOTAL);
    int gemm_blocks = (n_nodes + 127) / 128;
    gemm_mma_kernel<<<gemm_blocks, 256, SM_GEMM_TOTAL>>>(out, n_nodes);

    // ft_neighbor = A @ ft_input -> out[:, 256:512]  (fp16 gathers)
    int acc_blocks = (n_nodes * 32 + 255) / 256;
    accumulate_kernel<<<acc_blocks, 256>>>(out, n_nodes);
}